// round 4
// baseline (speedup 1.0000x reference)
#include <cuda_runtime.h>
#include <math.h>

// Problem constants (fixed by the dataset)
#define HH 512
#define WW 512
#define MAXV 2048
#define MAXF 4096
#define VIEW_TAN 0.5773502691896258f   // tan(30 deg)
#define NEARP 0.1f
#define BIGZ 1.0e10f
#define CH 256          // faces per culling chunk (= block size)
#define NBUK 256        // depth buckets
#define TILE_W 16
#define TILE_H 32       // 2 pixels per thread in y
#define NBX (WW / TILE_W)   // 32
#define NBY (HH / TILE_H)   // 16
#define NBLK (NBX * NBY)    // 512

// ---------------- device scratch (no allocations allowed) ----------------
__device__ float g_vx[MAXV];
__device__ float g_vy[MAXV];
__device__ float g_vz[MAXV];
// Per-face data, 3 x float4 = 12 floats:
//  FA = {A0, B0, C0, A1}
//  FB = {B1, C1, A2, B2}
//  FC = {C2, Z0*inv, Z1*inv, Z2*inv}
__device__ float4 g_FA[MAXF];
__device__ float4 g_FB[MAXF];
__device__ float4 g_FC[MAXF];
__device__ float4 g_BB[MAXF];    // bbox: xmin, ymin, xmax, ymax (NDC)
__device__ float4 g_COL[MAXF];
__device__ float  g_zmin[MAXF];
__device__ int    g_bkt[MAXF];
// bucket-sorted copies
__device__ float4 g_FA2[MAXF];
__device__ float4 g_FB2[MAXF];
__device__ float4 g_FC2[MAXF];
__device__ float4 g_BB2[MAXF];
__device__ int    g_idx2[MAXF];  // original face index
__device__ float  g_zact2[MAXF]; // actual zmin per sorted slot
__device__ float  g_lb2[MAXF];   // monotone bucket lower bound per slot
// bucket machinery
__device__ int    g_hist[NBUK + 1];
__device__ int    g_off[NBUK + 2];
__device__ int    g_cnt[NBUK + 1];
__device__ float  g_vzlo, g_vzhi;
__device__ float  g_partials[NBLK];

// ---------------- kernel 1: camera + vertex transform + z range ----------
__global__ __launch_bounds__(256)
void k_verts(const float* __restrict__ v,
             const float* __restrict__ campos,
             const float* __restrict__ camup,
             int nV) {
    __shared__ float R[9];
    __shared__ float eye[3];
    __shared__ float sLo[256], sHi[256];
    // zero bucket counters for this replay
    for (int i = threadIdx.x; i <= NBUK; i += 256) { g_hist[i] = 0; g_cnt[i] = 0; }
    if (threadIdx.x == 0) {
        float ex = campos[0], ey = campos[1], ez = campos[2];
        float nx = -ex, ny = -ey, nz = -ez;
        float nl = sqrtf(nx*nx + ny*ny + nz*nz) + 1e-12f;
        float zx = nx/nl, zy = ny/nl, zz = nz/nl;
        float ux = camup[0], uy = camup[1], uz = camup[2];
        float ul = sqrtf(ux*ux + uy*uy + uz*uz) + 1e-12f;
        ux /= ul; uy /= ul; uz /= ul;
        float cx = uy*zz - uz*zy;
        float cy = uz*zx - ux*zz;
        float cz = ux*zy - uy*zx;
        float cl = sqrtf(cx*cx + cy*cy + cz*cz) + 1e-12f;
        float xx = cx/cl, xy = cy/cl, xz = cz/cl;
        float yx = zy*xz - zz*xy;
        float yy = zz*xx - zx*xz;
        float yz = zx*xy - zy*xx;
        R[0]=xx; R[1]=xy; R[2]=xz;
        R[3]=yx; R[4]=yy; R[5]=yz;
        R[6]=zx; R[7]=zy; R[8]=zz;
        eye[0]=ex; eye[1]=ey; eye[2]=ez;
    }
    __syncthreads();
    float lo = 3.3e38f, hi = -3.3e38f;
    for (int i = threadIdx.x; i < nV; i += blockDim.x) {
        float ax = v[3*i+0] - eye[0];
        float ay = v[3*i+1] - eye[1];
        float az = v[3*i+2] - eye[2];
        float cxx = R[0]*ax + R[1]*ay + R[2]*az;
        float cyy = R[3]*ax + R[4]*ay + R[5]*az;
        float czz = R[6]*ax + R[7]*ay + R[8]*az;
        float d = czz * VIEW_TAN + 1e-12f;
        g_vx[i] = cxx / d;
        g_vy[i] = cyy / d;
        g_vz[i] = czz;
        lo = fminf(lo, czz);
        hi = fmaxf(hi, czz);
    }
    sLo[threadIdx.x] = lo;
    sHi[threadIdx.x] = hi;
    __syncthreads();
    for (int s = 128; s > 0; s >>= 1) {
        if (threadIdx.x < s) {
            sLo[threadIdx.x] = fminf(sLo[threadIdx.x], sLo[threadIdx.x + s]);
            sHi[threadIdx.x] = fmaxf(sHi[threadIdx.x], sHi[threadIdx.x + s]);
        }
        __syncthreads();
    }
    if (threadIdx.x == 0) { g_vzlo = sLo[0]; g_vzhi = sHi[0]; }
}

// ---------------- kernel 2: per-face setup + bucket histogram -------------
__global__ void k_faces(const int* __restrict__ faces,
                        const float* __restrict__ tex,
                        int nF) {
    int f = blockIdx.x * blockDim.x + threadIdx.x;
    if (f >= nF) return;
    int i0 = faces[3*f+0], i1 = faces[3*f+1], i2 = faces[3*f+2];
    float p0x = g_vx[i0], p0y = g_vy[i0], z0 = g_vz[i0];
    float p1x = g_vx[i1], p1y = g_vy[i1], z1 = g_vz[i1];
    float p2x = g_vx[i2], p2y = g_vy[i2], z2 = g_vz[i2];

    float area = (p1x-p0x)*(p2y-p0y) - (p1y-p0y)*(p2x-p0x);
    float zmn = fminf(z0, fminf(z1, z2));
    float zmx = fmaxf(z0, fmaxf(z1, z2));

    float4 FA, FB, FC, BB;
    bool live = (fabsf(area) > 1e-8f) && (zmx > NEARP);
    if (live) {
        float s   = (area > 0.0f) ? 1.0f : -1.0f;
        float inv = 1.0f / fabsf(area);
        float e0x = (p2x-p1x)*s, e0y = (p2y-p1y)*s;
        float A0 = -e0y, B0 = e0x, C0 = e0y*p1x - e0x*p1y;
        float e1x = (p0x-p2x)*s, e1y = (p0y-p2y)*s;
        float A1 = -e1y, B1 = e1x, C1 = e1y*p2x - e1x*p2y;
        float e2x = (p1x-p0x)*s, e2y = (p1y-p0y)*s;
        float A2 = -e2y, B2 = e2x, C2 = e2y*p0x - e2x*p0y;
        FA = make_float4(A0, B0, C0, A1);
        FB = make_float4(B1, C1, A2, B2);
        FC = make_float4(C2, z0*inv, z1*inv, z2*inv);
        BB = make_float4(fminf(p0x, fminf(p1x, p2x)),
                         fminf(p0y, fminf(p1y, p2y)),
                         fmaxf(p0x, fmaxf(p1x, p2x)),
                         fmaxf(p0y, fmaxf(p1y, p2y)));
    } else {
        FA = make_float4(0.f, 0.f, -1.f, 0.f);
        FB = make_float4(0.f, -1.f, 0.f, 0.f);
        FC = make_float4(-1.f, 0.f, 0.f, 0.f);
        BB = make_float4(2e9f, 2e9f, -2e9f, -2e9f);   // never overlaps any tile
        zmn = 3e38f;
    }
    g_FA[f] = FA; g_FB[f] = FB; g_FC[f] = FC; g_BB[f] = BB;
    g_zmin[f] = zmn;

    int b;
    if (live) {
        float w = g_vzhi - g_vzlo;
        float invw = (w > 0.f) ? ((float)NBUK / w) : 0.f;
        b = (int)((zmn - g_vzlo) * invw);
        b = max(0, min(NBUK - 1, b));
    } else {
        b = NBUK;   // overflow bucket at the very end
    }
    g_bkt[f] = b;
    atomicAdd(&g_hist[b], 1);

    const float* t = tex + (size_t)f * 24;
    float r = 0.f, g = 0.f, bl = 0.f;
    #pragma unroll
    for (int k = 0; k < 8; k++) {
        r += t[3*k+0]; g += t[3*k+1]; bl += t[3*k+2];
    }
    g_COL[f] = make_float4(r*0.125f, g*0.125f, bl*0.125f, 0.f);
}

// ---------------- kernel 3: exclusive scan over buckets ------------------
__global__ void k_scan() {
    if (threadIdx.x == 0) {
        int acc = 0;
        g_off[0] = 0;
        for (int i = 0; i <= NBUK; i++) {
            acc += g_hist[i];
            g_off[i + 1] = acc;
        }
    }
}

// ---------------- kernel 4: scatter into bucket order --------------------
__global__ void k_scatter(int nF) {
    int f = blockIdx.x * blockDim.x + threadIdx.x;
    if (f >= nF) return;
    int b = g_bkt[f];
    int pos = g_off[b] + atomicAdd(&g_cnt[b], 1);
    g_FA2[pos] = g_FA[f];
    g_FB2[pos] = g_FB[f];
    g_FC2[pos] = g_FC[f];
    g_BB2[pos] = g_BB[f];
    g_idx2[pos] = f;
    g_zact2[pos] = g_zmin[f];
    float lb;
    if (b >= NBUK) {
        lb = 3e38f;
    } else {
        float w = g_vzhi - g_vzlo;
        lb = g_vzlo + (float)b * w * (1.0f / NBUK) - 1e-5f;  // margin vs fp rounding
    }
    g_lb2[pos] = lb;
}

// ---------------- kernel 5: cull + front-to-back rasterize + loss ---------
__global__ __launch_bounds__(256)
void k_render(const float* __restrict__ image_ref, int nF) {
    __shared__ float4 sA[CH];
    __shared__ float4 sB[CH];
    __shared__ float4 sC[CH];
    __shared__ float  sZm[CH];
    __shared__ float  sLb[CH];
    __shared__ int    sIdx[CH];
    __shared__ int    sWcnt[8];
    __shared__ float  sWmax[8];
    __shared__ float  sBmax;
    __shared__ float  sRed[256];

    const int tx = threadIdx.x, ty = threadIdx.y;
    const int tid = ty * 16 + tx;
    const int wid = tid >> 5;
    const int lane = tid & 31;
    const int x  = blockIdx.x * TILE_W + tx;
    const int y0 = blockIdx.y * TILE_H + ty;

    const float px  = (x  + 0.5f) * (2.0f / WW) - 1.0f;
    const float py0 = 1.0f - (y0 + 0.5f) * (2.0f / HH);
    const float dpy = -16.0f * (2.0f / HH);        // py1 = py0 + dpy

    const float txmin = (blockIdx.x * TILE_W + 0.5f) * (2.0f / WW) - 1.0f;
    const float txmax = (blockIdx.x * TILE_W + TILE_W - 0.5f) * (2.0f / WW) - 1.0f;
    const float tymax = 1.0f - (blockIdx.y * TILE_H + 0.5f) * (2.0f / HH);
    const float tymin = 1.0f - (blockIdx.y * TILE_H + TILE_H - 0.5f) * (2.0f / HH);

    float zb0 = BIGZ, zb1 = BIGZ;
    int   b0  = -1,   b1  = -1;

    if (tid == 0) sBmax = BIGZ;
    __syncthreads();

    for (int base = 0; base < nF; base += CH) {
        // all remaining faces have zmin >= g_lb2[base] (monotone): if that
        // exceeds the farthest current winner in this tile, we're done.
        if (g_lb2[base] > sBmax) break;

        // --- order-preserving compaction (ballot + popc, no atomics) ---
        int f = base + tid;
        bool ok = false;
        if (f < nF) {
            float4 bb = g_BB2[f];
            ok = (bb.x <= txmax) && (bb.z >= txmin) &&
                 (bb.y <= tymax) && (bb.w >= tymin);
        }
        unsigned m = __ballot_sync(0xffffffffu, ok);
        if (lane == 0) sWcnt[wid] = __popc(m);
        __syncthreads();
        int wbase = 0;
        #pragma unroll
        for (int k = 0; k < 8; k++) wbase += (k < wid) ? sWcnt[k] : 0;
        int cnt = 0;
        #pragma unroll
        for (int k = 0; k < 8; k++) cnt += sWcnt[k];
        if (ok) {
            int p = wbase + __popc(m & ((1u << lane) - 1u));
            sIdx[p] = g_idx2[f];
            sZm[p]  = g_zact2[f];
            sLb[p]  = g_lb2[f];
            sA[p]   = g_FA2[f];
            sB[p]   = g_FB2[f];
            sC[p]   = g_FC2[f];
        }
        __syncthreads();

        // warp-wide upper bound on zbest (conservative, stale within chunk)
        float w = fmaxf(zb0, zb1);
        #pragma unroll
        for (int off = 16; off > 0; off >>= 1)
            w = fmaxf(w, __shfl_xor_sync(0xffffffffu, w, off));

        for (int i = 0; i < cnt; i++) {
            if (sLb[i] > w) break;      // monotone bound: rest of chunk dead
            if (sZm[i] > w) continue;   // this face alone cannot win
            float4 fa = sA[i];
            float4 fb = sB[i];
            float4 fc = sC[i];
            int    fi = sIdx[i];
            // pixel 0
            float u0 = fmaf(fa.x, px, fmaf(fa.y, py0, fa.z));
            float u1 = fmaf(fa.w, px, fmaf(fb.x, py0, fb.y));
            float u2 = fmaf(fb.z, px, fmaf(fb.w, py0, fc.x));
            float z  = fmaf(u0, fc.y, fmaf(u1, fc.z, u2 * fc.w));
            float mm = fminf(u0, fminf(u1, u2));
            if (mm >= 0.0f && z > NEARP &&
                (z < zb0 || (z == zb0 && fi < b0))) {
                zb0 = z; b0 = fi;
            }
            // pixel 1 (incremental in y)
            float v0 = fmaf(fa.y, dpy, u0);
            float v1 = fmaf(fb.x, dpy, u1);
            float v2 = fmaf(fb.w, dpy, u2);
            float z2 = fmaf(v0, fc.y, fmaf(v1, fc.z, v2 * fc.w));
            float m2 = fminf(v0, fminf(v1, v2));
            if (m2 >= 0.0f && z2 > NEARP &&
                (z2 < zb1 || (z2 == zb1 && fi < b1))) {
                zb1 = z2; b1 = fi;
            }
        }

        // refresh block-wide max zbest for the break test
        float mx = fmaxf(zb0, zb1);
        #pragma unroll
        for (int off = 16; off > 0; off >>= 1)
            mx = fmaxf(mx, __shfl_xor_sync(0xffffffffu, mx, off));
        if (lane == 0) sWmax[wid] = mx;
        __syncthreads();
        if (tid == 0) {
            float bm = sWmax[0];
            #pragma unroll
            for (int k = 1; k < 8; k++) bm = fmaxf(bm, sWmax[k]);
            sBmax = bm;
        }
        __syncthreads();
    }

    float loss = 0.f;
    {
        float r = 0.f, g = 0.f, b = 0.f;
        if (b0 >= 0) { float4 c = g_COL[b0]; r = c.x; g = c.y; b = c.z; }
        int ry = HH - 1 - y0;
        float d0 = r - image_ref[0*HH*WW + ry*WW + x];
        float d1 = g - image_ref[1*HH*WW + ry*WW + x];
        float d2 = b - image_ref[2*HH*WW + ry*WW + x];
        loss += d0*d0 + d1*d1 + d2*d2;
    }
    {
        float r = 0.f, g = 0.f, b = 0.f;
        if (b1 >= 0) { float4 c = g_COL[b1]; r = c.x; g = c.y; b = c.z; }
        int ry = HH - 1 - (y0 + 16);
        float d0 = r - image_ref[0*HH*WW + ry*WW + x];
        float d1 = g - image_ref[1*HH*WW + ry*WW + x];
        float d2 = b - image_ref[2*HH*WW + ry*WW + x];
        loss += d0*d0 + d1*d1 + d2*d2;
    }

    __syncthreads();
    sRed[tid] = loss;
    __syncthreads();
    #pragma unroll
    for (int s = 128; s > 0; s >>= 1) {
        if (tid < s) sRed[tid] += sRed[tid + s];
        __syncthreads();
    }
    if (tid == 0) g_partials[blockIdx.y * gridDim.x + blockIdx.x] = sRed[0];
}

// ---------------- kernel 6: final deterministic reduction ----------------
__global__ void k_reduce(float* __restrict__ out) {
    __shared__ float red[256];
    float s = 0.f;
    for (int i = threadIdx.x; i < NBLK; i += 256) s += g_partials[i];
    red[threadIdx.x] = s;
    __syncthreads();
    #pragma unroll
    for (int st = 128; st > 0; st >>= 1) {
        if (threadIdx.x < st) red[threadIdx.x] += red[threadIdx.x + st];
        __syncthreads();
    }
    if (threadIdx.x == 0) out[0] = red[0];
}

// ---------------- entry point ----------------
extern "C" void kernel_launch(void* const* d_in, const int* in_sizes, int n_in,
                              void* d_out, int out_size) {
    const float* v         = (const float*)d_in[0];   // (1, V, 3)
    const int*   faces     = (const int*)  d_in[1];   // (1, F, 3)
    const float* tex       = (const float*)d_in[2];   // (1, F, 2,2,2,3)
    const float* campos    = (const float*)d_in[3];   // (3,)
    const float* camup     = (const float*)d_in[4];   // (3,)
    const float* image_ref = (const float*)d_in[5];   // (1, 3, H, W)

    int nV = in_sizes[0] / 3;
    int nF = in_sizes[1] / 3;

    k_verts<<<1, 256>>>(v, campos, camup, nV);
    k_faces<<<(nF + 255) / 256, 256>>>(faces, tex, nF);
    k_scan<<<1, 32>>>();
    k_scatter<<<(nF + 255) / 256, 256>>>(nF);
    k_render<<<dim3(NBX, NBY), dim3(16, 16)>>>(image_ref, nF);
    k_reduce<<<1, 256>>>((float*)d_out);
}

// round 5
// speedup vs baseline: 1.7894x; 1.7894x over previous
#include <cuda_runtime.h>
#include <math.h>

// Problem constants (fixed by the dataset)
#define HH 512
#define WW 512
#define MAXV 2048
#define MAXF 4096
#define SORT_N 4096
#define VIEW_TAN 0.5773502691896258f   // tan(30 deg)
#define NEARP 0.1f
#define BIGZ 1.0e10f
#define CH 256          // faces per culling chunk (= block size)
#define TILE_W 16
#define TILE_H 32       // 2 pixels per thread in y
#define NBX (WW / TILE_W)   // 32
#define NBY (HH / TILE_H)   // 16
#define NBLK (NBX * NBY)    // 512

// ---------------- device scratch (no allocations allowed) ----------------
__device__ float g_vx[MAXV];
__device__ float g_vy[MAXV];
__device__ float g_vz[MAXV];
// Per-face data, 3 x float4 = 12 floats:
//  FA = {A0, B0, C0, A1}
//  FB = {B1, C1, A2, B2}
//  FC = {C2, Z0*inv, Z1*inv, Z2*inv}
__device__ float4 g_FA[MAXF];
__device__ float4 g_FB[MAXF];
__device__ float4 g_FC[MAXF];
__device__ float4 g_BB[MAXF];    // bbox: xmin, ymin, xmax, ymax (NDC)
__device__ float4 g_COL[MAXF];
__device__ float  g_zmin[MAXF];
// z-sorted copies
__device__ float4 g_FA2[MAXF];
__device__ float4 g_FB2[MAXF];
__device__ float4 g_FC2[MAXF];
__device__ float4 g_BB2[MAXF];
__device__ int    g_idx2[MAXF];  // original face index
__device__ float  g_zminS[MAXF];
__device__ int    g_ord[MAXF];
__device__ float  g_partials[NBLK];

// ---------------- kernel 1: camera + vertex transform ----------------
__global__ void k_verts(const float* __restrict__ v,
                        const float* __restrict__ campos,
                        const float* __restrict__ camup,
                        int nV) {
    __shared__ float R[9];
    __shared__ float eye[3];
    if (threadIdx.x == 0) {
        float ex = campos[0], ey = campos[1], ez = campos[2];
        float nx = -ex, ny = -ey, nz = -ez;
        float nl = sqrtf(nx*nx + ny*ny + nz*nz) + 1e-12f;
        float zx = nx/nl, zy = ny/nl, zz = nz/nl;
        float ux = camup[0], uy = camup[1], uz = camup[2];
        float ul = sqrtf(ux*ux + uy*uy + uz*uz) + 1e-12f;
        ux /= ul; uy /= ul; uz /= ul;
        float cx = uy*zz - uz*zy;
        float cy = uz*zx - ux*zz;
        float cz = ux*zy - uy*zx;
        float cl = sqrtf(cx*cx + cy*cy + cz*cz) + 1e-12f;
        float xx = cx/cl, xy = cy/cl, xz = cz/cl;
        float yx = zy*xz - zz*xy;
        float yy = zz*xx - zx*xz;
        float yz = zx*xy - zy*xx;
        R[0]=xx; R[1]=xy; R[2]=xz;
        R[3]=yx; R[4]=yy; R[5]=yz;
        R[6]=zx; R[7]=zy; R[8]=zz;
        eye[0]=ex; eye[1]=ey; eye[2]=ez;
    }
    __syncthreads();
    for (int i = threadIdx.x; i < nV; i += blockDim.x) {
        float ax = v[3*i+0] - eye[0];
        float ay = v[3*i+1] - eye[1];
        float az = v[3*i+2] - eye[2];
        float cxx = R[0]*ax + R[1]*ay + R[2]*az;
        float cyy = R[3]*ax + R[4]*ay + R[5]*az;
        float czz = R[6]*ax + R[7]*ay + R[8]*az;
        float d = czz * VIEW_TAN + 1e-12f;
        g_vx[i] = cxx / d;
        g_vy[i] = cyy / d;
        g_vz[i] = czz;
    }
}

// ---------------- kernel 2: per-face setup (edges, z coeffs, bbox, color) ----
__global__ void k_faces(const int* __restrict__ faces,
                        const float* __restrict__ tex,
                        int nF) {
    int f = blockIdx.x * blockDim.x + threadIdx.x;
    if (f >= nF) return;
    int i0 = faces[3*f+0], i1 = faces[3*f+1], i2 = faces[3*f+2];
    float p0x = g_vx[i0], p0y = g_vy[i0], z0 = g_vz[i0];
    float p1x = g_vx[i1], p1y = g_vy[i1], z1 = g_vz[i1];
    float p2x = g_vx[i2], p2y = g_vy[i2], z2 = g_vz[i2];

    float area = (p1x-p0x)*(p2y-p0y) - (p1y-p0y)*(p2x-p0x);
    float zmn = fminf(z0, fminf(z1, z2));
    float zmx = fmaxf(z0, fmaxf(z1, z2));

    float4 FA, FB, FC, BB;
    bool live = (fabsf(area) > 1e-8f) && (zmx > NEARP);
    if (live) {
        float s   = (area > 0.0f) ? 1.0f : -1.0f;
        float inv = 1.0f / fabsf(area);
        float e0x = (p2x-p1x)*s, e0y = (p2y-p1y)*s;
        float A0 = -e0y, B0 = e0x, C0 = e0y*p1x - e0x*p1y;
        float e1x = (p0x-p2x)*s, e1y = (p0y-p2y)*s;
        float A1 = -e1y, B1 = e1x, C1 = e1y*p2x - e1x*p2y;
        float e2x = (p1x-p0x)*s, e2y = (p1y-p0y)*s;
        float A2 = -e2y, B2 = e2x, C2 = e2y*p0x - e2x*p0y;
        FA = make_float4(A0, B0, C0, A1);
        FB = make_float4(B1, C1, A2, B2);
        FC = make_float4(C2, z0*inv, z1*inv, z2*inv);
        BB = make_float4(fminf(p0x, fminf(p1x, p2x)),
                         fminf(p0y, fminf(p1y, p2y)),
                         fmaxf(p0x, fmaxf(p1x, p2x)),
                         fmaxf(p0y, fmaxf(p1y, p2y)));
    } else {
        FA = make_float4(0.f, 0.f, -1.f, 0.f);
        FB = make_float4(0.f, -1.f, 0.f, 0.f);
        FC = make_float4(-1.f, 0.f, 0.f, 0.f);
        BB = make_float4(2e9f, 2e9f, -2e9f, -2e9f);   // never overlaps any tile
        zmn = 3e38f;                                   // sorts to the very end
    }
    g_FA[f] = FA; g_FB[f] = FB; g_FC[f] = FC; g_BB[f] = BB;
    g_zmin[f] = zmn;

    const float* t = tex + (size_t)f * 24;
    float r = 0.f, g = 0.f, b = 0.f;
    #pragma unroll
    for (int k = 0; k < 8; k++) {
        r += t[3*k+0]; g += t[3*k+1]; b += t[3*k+2];
    }
    g_COL[f] = make_float4(r*0.125f, g*0.125f, b*0.125f, 0.f);
}

// ---------------- kernel 3: bitonic sort by zmin (single block) ----------
__global__ __launch_bounds__(1024)
void k_sort(int nF) {
    __shared__ float key[SORT_N];
    __shared__ int   val[SORT_N];
    const int t = threadIdx.x;
    for (int i = t; i < SORT_N; i += 1024) {
        key[i] = (i < nF) ? g_zmin[i] : 3.3e38f;
        val[i] = i;
    }
    __syncthreads();
    for (int k = 2; k <= SORT_N; k <<= 1) {
        for (int j = k >> 1; j > 0; j >>= 1) {
            for (int i = t; i < SORT_N; i += 1024) {
                int ixj = i ^ j;
                if (ixj > i) {
                    bool up = ((i & k) == 0);
                    float a = key[i], b = key[ixj];
                    if (up ? (a > b) : (a < b)) {
                        key[i] = b; key[ixj] = a;
                        int tv = val[i]; val[i] = val[ixj]; val[ixj] = tv;
                    }
                }
            }
            __syncthreads();
        }
    }
    for (int i = t; i < SORT_N; i += 1024) {
        g_ord[i]   = val[i];
        g_zminS[i] = key[i];
    }
}

// ---------------- kernel 4: scatter face data into sorted order ----------
__global__ void k_reorder(int nF) {
    int i = blockIdx.x * blockDim.x + threadIdx.x;
    if (i >= nF) return;
    int f = g_ord[i];
    g_FA2[i] = g_FA[f];
    g_FB2[i] = g_FB[f];
    g_FC2[i] = g_FC[f];
    g_BB2[i] = g_BB[f];
    g_idx2[i] = f;
}

// ---------------- kernel 5: cull + front-to-back rasterize + loss ---------
__global__ __launch_bounds__(256)
void k_render(const float* __restrict__ image_ref, int nF) {
    __shared__ float4 sA[CH];
    __shared__ float4 sB[CH];
    __shared__ float4 sC[CH];
    __shared__ float  sZm[CH];
    __shared__ int    sIdx[CH];
    __shared__ int    sCnt;
    __shared__ float  sWmax[8];
    __shared__ float  sBmax;
    __shared__ float  sRed[256];

    const int tx = threadIdx.x, ty = threadIdx.y;
    const int tid = ty * 16 + tx;
    const int wid = tid >> 5;
    const int x  = blockIdx.x * TILE_W + tx;
    const int y0 = blockIdx.y * TILE_H + ty;

    const float px  = (x  + 0.5f) * (2.0f / WW) - 1.0f;
    const float py0 = 1.0f - (y0 + 0.5f) * (2.0f / HH);
    const float dpy = -16.0f * (2.0f / HH);        // py1 = py0 + dpy

    // tile pixel-center bounds (NDC)
    const float txmin = (blockIdx.x * TILE_W + 0.5f) * (2.0f / WW) - 1.0f;
    const float txmax = (blockIdx.x * TILE_W + TILE_W - 0.5f) * (2.0f / WW) - 1.0f;
    const float tymax = 1.0f - (blockIdx.y * TILE_H + 0.5f) * (2.0f / HH);
    const float tymin = 1.0f - (blockIdx.y * TILE_H + TILE_H - 0.5f) * (2.0f / HH);
    // tile center / half extents for edge-rect rejection
    const float tcx = 0.5f * (txmin + txmax);
    const float tcy = 0.5f * (tymin + tymax);
    const float thx = 0.5f * (txmax - txmin);
    const float thy = 0.5f * (tymax - tymin);

    float zb0 = BIGZ, zb1 = BIGZ;
    int   b0  = -1,   b1  = -1;

    if (tid == 0) sBmax = BIGZ;
    __syncthreads();

    for (int base = 0; base < nF; base += CH) {
        // all remaining faces have zmin >= g_zminS[base]; if that exceeds the
        // farthest current winner in this tile, nothing can change -> done.
        float zCap = sBmax;
        if (g_zminS[base] > zCap) break;

        if (tid == 0) sCnt = 0;
        __syncthreads();

        int f = base + tid;
        if (f < nF) {
            float4 bb = g_BB2[f];
            float zmn = g_zminS[f];
            bool ok = (bb.x <= txmax) && (bb.z >= txmin) &&
                      (bb.y <= tymax) && (bb.w >= tymin) &&
                      (zmn <= zCap);
            if (ok) {
                float4 fa = g_FA2[f];
                float4 fb = g_FB2[f];
                float4 fc = g_FC2[f];
                // exact tile-rect vs triangle: for each edge half-plane,
                // max over rect of u_e = u_e(center) + |A|hx + |B|hy.
                // if any edge max < 0 -> no pixel center can be inside.
                float u0c = fmaf(fa.x, tcx, fmaf(fa.y, tcy, fa.z));
                float m0  = fmaf(fabsf(fa.x), thx, fmaf(fabsf(fa.y), thy, u0c));
                float u1c = fmaf(fa.w, tcx, fmaf(fb.x, tcy, fb.y));
                float m1  = fmaf(fabsf(fa.w), thx, fmaf(fabsf(fb.x), thy, u1c));
                float u2c = fmaf(fb.z, tcx, fmaf(fb.w, tcy, fc.x));
                float m2  = fmaf(fabsf(fb.z), thx, fmaf(fabsf(fb.w), thy, u2c));
                // conservative margins (relative) so rounding never culls a winner
                bool keep = (m0 >= -1e-5f * fmaxf(1.0f, fabsf(u0c))) &&
                            (m1 >= -1e-5f * fmaxf(1.0f, fabsf(u1c))) &&
                            (m2 >= -1e-5f * fmaxf(1.0f, fabsf(u2c)));
                if (keep) {
                    int p = atomicAdd(&sCnt, 1);
                    sIdx[p] = g_idx2[f];
                    sZm[p]  = zmn;
                    sA[p]   = fa;
                    sB[p]   = fb;
                    sC[p]   = fc;
                }
            }
        }
        __syncthreads();
        int cnt = sCnt;

        // warp-wide upper bound on zbest (conservative, stale within chunk)
        float w = fmaxf(zb0, zb1);
        #pragma unroll
        for (int off = 16; off > 0; off >>= 1)
            w = fmaxf(w, __shfl_xor_sync(0xffffffffu, w, off));

        for (int i = 0; i < cnt; i++) {
            if (sZm[i] > w) continue;   // warp-uniform skip: face can't win
            float4 fa = sA[i];
            float4 fb = sB[i];
            float4 fc = sC[i];
            int    fi = sIdx[i];
            // pixel 0
            float u0 = fmaf(fa.x, px, fmaf(fa.y, py0, fa.z));
            float u1 = fmaf(fa.w, px, fmaf(fb.x, py0, fb.y));
            float u2 = fmaf(fb.z, px, fmaf(fb.w, py0, fc.x));
            float z  = fmaf(u0, fc.y, fmaf(u1, fc.z, u2 * fc.w));
            float mm = fminf(u0, fminf(u1, u2));
            if (mm >= 0.0f && z > NEARP &&
                (z < zb0 || (z == zb0 && fi < b0))) {
                zb0 = z; b0 = fi;
            }
            // pixel 1 (incremental in y)
            float v0 = fmaf(fa.y, dpy, u0);
            float v1 = fmaf(fb.x, dpy, u1);
            float v2 = fmaf(fb.w, dpy, u2);
            float z2 = fmaf(v0, fc.y, fmaf(v1, fc.z, v2 * fc.w));
            float m2 = fminf(v0, fminf(v1, v2));
            if (m2 >= 0.0f && z2 > NEARP &&
                (z2 < zb1 || (z2 == zb1 && fi < b1))) {
                zb1 = z2; b1 = fi;
            }
        }

        // refresh block-wide max zbest for the break test
        float m = fmaxf(zb0, zb1);
        #pragma unroll
        for (int off = 16; off > 0; off >>= 1)
            m = fmaxf(m, __shfl_xor_sync(0xffffffffu, m, off));
        if ((tid & 31) == 0) sWmax[wid] = m;
        __syncthreads();
        if (tid == 0) {
            float bm = sWmax[0];
            #pragma unroll
            for (int k = 1; k < 8; k++) bm = fmaxf(bm, sWmax[k]);
            sBmax = bm;
        }
        __syncthreads();
    }

    float loss = 0.f;
    {
        float r = 0.f, g = 0.f, b = 0.f;
        if (b0 >= 0) { float4 c = g_COL[b0]; r = c.x; g = c.y; b = c.z; }
        int ry = HH - 1 - y0;
        float d0 = r - image_ref[0*HH*WW + ry*WW + x];
        float d1 = g - image_ref[1*HH*WW + ry*WW + x];
        float d2 = b - image_ref[2*HH*WW + ry*WW + x];
        loss += d0*d0 + d1*d1 + d2*d2;
    }
    {
        float r = 0.f, g = 0.f, b = 0.f;
        if (b1 >= 0) { float4 c = g_COL[b1]; r = c.x; g = c.y; b = c.z; }
        int ry = HH - 1 - (y0 + 16);
        float d0 = r - image_ref[0*HH*WW + ry*WW + x];
        float d1 = g - image_ref[1*HH*WW + ry*WW + x];
        float d2 = b - image_ref[2*HH*WW + ry*WW + x];
        loss += d0*d0 + d1*d1 + d2*d2;
    }

    __syncthreads();
    sRed[tid] = loss;
    __syncthreads();
    #pragma unroll
    for (int s = 128; s > 0; s >>= 1) {
        if (tid < s) sRed[tid] += sRed[tid + s];
        __syncthreads();
    }
    if (tid == 0) g_partials[blockIdx.y * gridDim.x + blockIdx.x] = sRed[0];
}

// ---------------- kernel 6: final deterministic reduction ----------------
__global__ void k_reduce(float* __restrict__ out) {
    __shared__ float red[256];
    float s = 0.f;
    for (int i = threadIdx.x; i < NBLK; i += 256) s += g_partials[i];
    red[threadIdx.x] = s;
    __syncthreads();
    #pragma unroll
    for (int st = 128; st > 0; st >>= 1) {
        if (threadIdx.x < st) red[threadIdx.x] += red[threadIdx.x + st];
        __syncthreads();
    }
    if (threadIdx.x == 0) out[0] = red[0];
}

// ---------------- entry point ----------------
extern "C" void kernel_launch(void* const* d_in, const int* in_sizes, int n_in,
                              void* d_out, int out_size) {
    const float* v         = (const float*)d_in[0];   // (1, V, 3)
    const int*   faces     = (const int*)  d_in[1];   // (1, F, 3)
    const float* tex       = (const float*)d_in[2];   // (1, F, 2,2,2,3)
    const float* campos    = (const float*)d_in[3];   // (3,)
    const float* camup     = (const float*)d_in[4];   // (3,)
    const float* image_ref = (const float*)d_in[5];   // (1, 3, H, W)

    int nV = in_sizes[0] / 3;
    int nF = in_sizes[1] / 3;

    k_verts<<<1, 256>>>(v, campos, camup, nV);
    k_faces<<<(nF + 255) / 256, 256>>>(faces, tex, nF);
    k_sort<<<1, 1024>>>(nF);
    k_reorder<<<(nF + 255) / 256, 256>>>(nF);
    k_render<<<dim3(NBX, NBY), dim3(16, 16)>>>(image_ref, nF);
    k_reduce<<<1, 256>>>((float*)d_out);
}

// round 7
// speedup vs baseline: 2.7616x; 1.5433x over previous
#include <cuda_runtime.h>
#include <math.h>

// Problem constants (fixed by the dataset)
#define HH 512
#define WW 512
#define MAXV 2048
#define MAXF 4096
#define VIEW_TAN 0.5773502691896258f   // tan(30 deg)
#define NEARP 0.1f
#define BIGZ 1.0e10f
#define CH 256          // faces per culling chunk (= block size)
#define NBUK 256        // depth buckets
#define TILE_W 16
#define TILE_H 32       // 2 pixels per thread in y
#define NBX (WW / TILE_W)   // 32
#define NBY (HH / TILE_H)   // 16
#define NBLK (NBX * NBY)    // 512

// ---------------- device scratch (no allocations allowed) ----------------
__device__ float g_vx[MAXV];
__device__ float g_vy[MAXV];
__device__ float g_vz[MAXV];
// Per-face data, 3 x float4 = 12 floats:
//  FA = {A0, B0, C0, A1}
//  FB = {B1, C1, A2, B2}
//  FC = {C2, Z0*inv, Z1*inv, Z2*inv}
__device__ float4 g_FA[MAXF];
__device__ float4 g_FB[MAXF];
__device__ float4 g_FC[MAXF];
__device__ float4 g_BB[MAXF];    // bbox: xmin, ymin, xmax, ymax (NDC)
__device__ float4 g_COL[MAXF];
__device__ float  g_zmin[MAXF];
__device__ int    g_bkt[MAXF];
// bucket-sorted copies
__device__ float4 g_FA2[MAXF];
__device__ float4 g_FB2[MAXF];
__device__ float4 g_FC2[MAXF];
__device__ float4 g_BB2[MAXF];
__device__ int    g_idx2[MAXF];  // original face index
__device__ float  g_zminS[MAXF]; // ACTUAL face zmin per sorted slot
__device__ float  g_lbS[MAXF];   // monotone bucket lower bound per slot
// bucket machinery
__device__ int    g_hist[NBUK + 1];
__device__ int    g_off[NBUK + 2];
__device__ int    g_cnt[NBUK + 1];
__device__ float  g_vzlo, g_vzhi;
__device__ float  g_partials[NBLK];

// ---------------- kernel 1: camera + vertex transform + z range ----------
__global__ __launch_bounds__(256)
void k_verts(const float* __restrict__ v,
             const float* __restrict__ campos,
             const float* __restrict__ camup,
             int nV) {
    __shared__ float R[9];
    __shared__ float eye[3];
    __shared__ float sLo[256], sHi[256];
    // zero bucket counters for this replay
    for (int i = threadIdx.x; i <= NBUK; i += 256) { g_hist[i] = 0; g_cnt[i] = 0; }
    if (threadIdx.x == 0) {
        float ex = campos[0], ey = campos[1], ez = campos[2];
        float nx = -ex, ny = -ey, nz = -ez;
        float nl = sqrtf(nx*nx + ny*ny + nz*nz) + 1e-12f;
        float zx = nx/nl, zy = ny/nl, zz = nz/nl;
        float ux = camup[0], uy = camup[1], uz = camup[2];
        float ul = sqrtf(ux*ux + uy*uy + uz*uz) + 1e-12f;
        ux /= ul; uy /= ul; uz /= ul;
        float cx = uy*zz - uz*zy;
        float cy = uz*zx - ux*zz;
        float cz = ux*zy - uy*zx;
        float cl = sqrtf(cx*cx + cy*cy + cz*cz) + 1e-12f;
        float xx = cx/cl, xy = cy/cl, xz = cz/cl;
        float yx = zy*xz - zz*xy;
        float yy = zz*xx - zx*xz;
        float yz = zx*xy - zy*xx;
        R[0]=xx; R[1]=xy; R[2]=xz;
        R[3]=yx; R[4]=yy; R[5]=yz;
        R[6]=zx; R[7]=zy; R[8]=zz;
        eye[0]=ex; eye[1]=ey; eye[2]=ez;
    }
    __syncthreads();
    float lo = 3.3e38f, hi = -3.3e38f;
    for (int i = threadIdx.x; i < nV; i += blockDim.x) {
        float ax = v[3*i+0] - eye[0];
        float ay = v[3*i+1] - eye[1];
        float az = v[3*i+2] - eye[2];
        float cxx = R[0]*ax + R[1]*ay + R[2]*az;
        float cyy = R[3]*ax + R[4]*ay + R[5]*az;
        float czz = R[6]*ax + R[7]*ay + R[8]*az;
        float d = czz * VIEW_TAN + 1e-12f;
        g_vx[i] = cxx / d;
        g_vy[i] = cyy / d;
        g_vz[i] = czz;
        lo = fminf(lo, czz);
        hi = fmaxf(hi, czz);
    }
    sLo[threadIdx.x] = lo;
    sHi[threadIdx.x] = hi;
    __syncthreads();
    for (int s = 128; s > 0; s >>= 1) {
        if (threadIdx.x < s) {
            sLo[threadIdx.x] = fminf(sLo[threadIdx.x], sLo[threadIdx.x + s]);
            sHi[threadIdx.x] = fmaxf(sHi[threadIdx.x], sHi[threadIdx.x + s]);
        }
        __syncthreads();
    }
    if (threadIdx.x == 0) { g_vzlo = sLo[0]; g_vzhi = sHi[0]; }
}

// ---------------- kernel 2: per-face setup + bucket histogram -------------
__global__ void k_faces(const int* __restrict__ faces,
                        const float* __restrict__ tex,
                        int nF) {
    int f = blockIdx.x * blockDim.x + threadIdx.x;
    if (f >= nF) return;
    int i0 = faces[3*f+0], i1 = faces[3*f+1], i2 = faces[3*f+2];
    float p0x = g_vx[i0], p0y = g_vy[i0], z0 = g_vz[i0];
    float p1x = g_vx[i1], p1y = g_vy[i1], z1 = g_vz[i1];
    float p2x = g_vx[i2], p2y = g_vy[i2], z2 = g_vz[i2];

    float area = (p1x-p0x)*(p2y-p0y) - (p1y-p0y)*(p2x-p0x);
    float zmn = fminf(z0, fminf(z1, z2));
    float zmx = fmaxf(z0, fmaxf(z1, z2));

    float4 FA, FB, FC, BB;
    bool live = (fabsf(area) > 1e-8f) && (zmx > NEARP);
    if (live) {
        float s   = (area > 0.0f) ? 1.0f : -1.0f;
        float inv = 1.0f / fabsf(area);
        float e0x = (p2x-p1x)*s, e0y = (p2y-p1y)*s;
        float A0 = -e0y, B0 = e0x, C0 = e0y*p1x - e0x*p1y;
        float e1x = (p0x-p2x)*s, e1y = (p0y-p2y)*s;
        float A1 = -e1y, B1 = e1x, C1 = e1y*p2x - e1x*p2y;
        float e2x = (p1x-p0x)*s, e2y = (p1y-p0y)*s;
        float A2 = -e2y, B2 = e2x, C2 = e2y*p0x - e2x*p0y;
        FA = make_float4(A0, B0, C0, A1);
        FB = make_float4(B1, C1, A2, B2);
        FC = make_float4(C2, z0*inv, z1*inv, z2*inv);
        BB = make_float4(fminf(p0x, fminf(p1x, p2x)),
                         fminf(p0y, fminf(p1y, p2y)),
                         fmaxf(p0x, fmaxf(p1x, p2x)),
                         fmaxf(p0y, fmaxf(p1y, p2y)));
    } else {
        FA = make_float4(0.f, 0.f, -1.f, 0.f);
        FB = make_float4(0.f, -1.f, 0.f, 0.f);
        FC = make_float4(-1.f, 0.f, 0.f, 0.f);
        BB = make_float4(2e9f, 2e9f, -2e9f, -2e9f);   // never overlaps any tile
        zmn = 3e38f;
    }
    g_FA[f] = FA; g_FB[f] = FB; g_FC[f] = FC; g_BB[f] = BB;
    g_zmin[f] = zmn;

    int b;
    if (live) {
        float w = g_vzhi - g_vzlo;
        float invw = (w > 0.f) ? ((float)NBUK / w) : 0.f;
        b = (int)((zmn - g_vzlo) * invw);
        b = max(0, min(NBUK - 1, b));
    } else {
        b = NBUK;   // overflow bucket at the very end
    }
    g_bkt[f] = b;
    atomicAdd(&g_hist[b], 1);

    const float* t = tex + (size_t)f * 24;
    float r = 0.f, g = 0.f, bl = 0.f;
    #pragma unroll
    for (int k = 0; k < 8; k++) {
        r += t[3*k+0]; g += t[3*k+1]; bl += t[3*k+2];
    }
    g_COL[f] = make_float4(r*0.125f, g*0.125f, bl*0.125f, 0.f);
}

// ---------------- kernel 3: exclusive scan over buckets (1 warp) ---------
__global__ void k_scan() {
    const int lane = threadIdx.x;   // 32 threads
    int acc = 0;
    for (int base = 0; base <= NBUK; base += 32) {
        int i = base + lane;
        int vv = (i <= NBUK) ? g_hist[i] : 0;
        // inclusive warp scan
        int sc = vv;
        #pragma unroll
        for (int d = 1; d < 32; d <<= 1) {
            int n = __shfl_up_sync(0xffffffffu, sc, d);
            if (lane >= d) sc += n;
        }
        if (i <= NBUK) g_off[i + 1] = acc + sc;
        int tot = __shfl_sync(0xffffffffu, sc, 31);
        acc += tot;
    }
    if (lane == 0) g_off[0] = 0;
}

// ---------------- kernel 4: scatter into bucket order --------------------
__global__ void k_scatter(int nF) {
    int f = blockIdx.x * blockDim.x + threadIdx.x;
    if (f >= nF) return;
    int b = g_bkt[f];
    int pos = g_off[b] + atomicAdd(&g_cnt[b], 1);
    g_FA2[pos] = g_FA[f];
    g_FB2[pos] = g_FB[f];
    g_FC2[pos] = g_FC[f];
    g_BB2[pos] = g_BB[f];
    g_idx2[pos] = f;
    g_zminS[pos] = g_zmin[f];
    float lb;
    if (b >= NBUK) {
        lb = 3e38f;
    } else {
        float w = g_vzhi - g_vzlo;
        lb = g_vzlo + (float)b * w * (1.0f / NBUK) - 1e-5f;  // fp-rounding margin
    }
    g_lbS[pos] = lb;
}

// ---------------- kernel 5: cull + front-to-back rasterize + loss ---------
__global__ __launch_bounds__(256)
void k_render(const float* __restrict__ image_ref, int nF) {
    __shared__ float4 sA[CH];
    __shared__ float4 sB[CH];
    __shared__ float4 sC[CH];
    __shared__ float  sZm[CH];
    __shared__ int    sIdx[CH];
    __shared__ int    sCnt;
    __shared__ float  sWmax[8];
    __shared__ float  sBmax;
    __shared__ float  sRed[256];

    const int tx = threadIdx.x, ty = threadIdx.y;
    const int tid = ty * 16 + tx;
    const int wid = tid >> 5;
    const int x  = blockIdx.x * TILE_W + tx;
    const int y0 = blockIdx.y * TILE_H + ty;

    const float px  = (x  + 0.5f) * (2.0f / WW) - 1.0f;
    const float py0 = 1.0f - (y0 + 0.5f) * (2.0f / HH);
    const float dpy = -16.0f * (2.0f / HH);        // py1 = py0 + dpy

    // tile pixel-center bounds (NDC)
    const float txmin = (blockIdx.x * TILE_W + 0.5f) * (2.0f / WW) - 1.0f;
    const float txmax = (blockIdx.x * TILE_W + TILE_W - 0.5f) * (2.0f / WW) - 1.0f;
    const float tymax = 1.0f - (blockIdx.y * TILE_H + 0.5f) * (2.0f / HH);
    const float tymin = 1.0f - (blockIdx.y * TILE_H + TILE_H - 0.5f) * (2.0f / HH);
    // tile center / half extents for edge-rect rejection
    const float tcx = 0.5f * (txmin + txmax);
    const float tcy = 0.5f * (tymin + tymax);
    const float thx = 0.5f * (txmax - txmin);
    const float thy = 0.5f * (tymax - tymin);

    float zb0 = BIGZ, zb1 = BIGZ;
    int   b0  = -1,   b1  = -1;

    if (tid == 0) sBmax = BIGZ;
    __syncthreads();

    for (int base = 0; base < nF; base += CH) {
        // all remaining slots have zmin >= g_lbS[base] (monotone): if that
        // exceeds the farthest current winner in this tile, we're done.
        float zCap = sBmax;
        if (g_lbS[base] > zCap) break;

        if (tid == 0) sCnt = 0;
        __syncthreads();

        int f = base + tid;
        if (f < nF) {
            float4 bb = g_BB2[f];
            float zmn = g_zminS[f];
            bool ok = (bb.x <= txmax) && (bb.z >= txmin) &&
                      (bb.y <= tymax) && (bb.w >= tymin) &&
                      (zmn <= zCap);
            if (ok) {
                float4 fa = g_FA2[f];
                float4 fb = g_FB2[f];
                float4 fc = g_FC2[f];
                // exact tile-rect vs triangle: for each edge half-plane,
                // max over rect of u_e = u_e(center) + |A|hx + |B|hy.
                // if any edge max < 0 -> no pixel center can be inside.
                float u0c = fmaf(fa.x, tcx, fmaf(fa.y, tcy, fa.z));
                float m0  = fmaf(fabsf(fa.x), thx, fmaf(fabsf(fa.y), thy, u0c));
                float u1c = fmaf(fa.w, tcx, fmaf(fb.x, tcy, fb.y));
                float m1  = fmaf(fabsf(fa.w), thx, fmaf(fabsf(fb.x), thy, u1c));
                float u2c = fmaf(fb.z, tcx, fmaf(fb.w, tcy, fc.x));
                float m2  = fmaf(fabsf(fb.z), thx, fmaf(fabsf(fb.w), thy, u2c));
                // conservative margins (relative) so rounding never culls a winner
                bool keep = (m0 >= -1e-5f * fmaxf(1.0f, fabsf(u0c))) &&
                            (m1 >= -1e-5f * fmaxf(1.0f, fabsf(u1c))) &&
                            (m2 >= -1e-5f * fmaxf(1.0f, fabsf(u2c)));
                if (keep) {
                    int p = atomicAdd(&sCnt, 1);
                    sIdx[p] = g_idx2[f];
                    sZm[p]  = zmn;
                    sA[p]   = fa;
                    sB[p]   = fb;
                    sC[p]   = fc;
                }
            }
        }
        __syncthreads();
        int cnt = sCnt;

        // warp-wide upper bound on zbest (conservative, stale within chunk)
        float w = fmaxf(zb0, zb1);
        #pragma unroll
        for (int off = 16; off > 0; off >>= 1)
            w = fmaxf(w, __shfl_xor_sync(0xffffffffu, w, off));

        for (int i = 0; i < cnt; i++) {
            if (sZm[i] > w) continue;   // warp-uniform skip: face can't win
            float4 fa = sA[i];
            float4 fb = sB[i];
            float4 fc = sC[i];
            int    fi = sIdx[i];
            // pixel 0
            float u0 = fmaf(fa.x, px, fmaf(fa.y, py0, fa.z));
            float u1 = fmaf(fa.w, px, fmaf(fb.x, py0, fb.y));
            float u2 = fmaf(fb.z, px, fmaf(fb.w, py0, fc.x));
            float z  = fmaf(u0, fc.y, fmaf(u1, fc.z, u2 * fc.w));
            float mm = fminf(u0, fminf(u1, u2));
            if (mm >= 0.0f && z > NEARP &&
                (z < zb0 || (z == zb0 && fi < b0))) {
                zb0 = z; b0 = fi;
            }
            // pixel 1 (incremental in y)
            float v0 = fmaf(fa.y, dpy, u0);
            float v1 = fmaf(fb.x, dpy, u1);
            float v2 = fmaf(fb.w, dpy, u2);
            float z2 = fmaf(v0, fc.y, fmaf(v1, fc.z, v2 * fc.w));
            float m2 = fminf(v0, fminf(v1, v2));
            if (m2 >= 0.0f && z2 > NEARP &&
                (z2 < zb1 || (z2 == zb1 && fi < b1))) {
                zb1 = z2; b1 = fi;
            }
        }

        // refresh block-wide max zbest for the break test
        float m = fmaxf(zb0, zb1);
        #pragma unroll
        for (int off = 16; off > 0; off >>= 1)
            m = fmaxf(m, __shfl_xor_sync(0xffffffffu, m, off));
        if ((tid & 31) == 0) sWmax[wid] = m;
        __syncthreads();
        if (tid == 0) {
            float bm = sWmax[0];
            #pragma unroll
            for (int k = 1; k < 8; k++) bm = fmaxf(bm, sWmax[k]);
            sBmax = bm;
        }
        __syncthreads();
    }

    float loss = 0.f;
    {
        float r = 0.f, g = 0.f, b = 0.f;
        if (b0 >= 0) { float4 c = g_COL[b0]; r = c.x; g = c.y; b = c.z; }
        int ry = HH - 1 - y0;
        float d0 = r - image_ref[0*HH*WW + ry*WW + x];
        float d1 = g - image_ref[1*HH*WW + ry*WW + x];
        float d2 = b - image_ref[2*HH*WW + ry*WW + x];
        loss += d0*d0 + d1*d1 + d2*d2;
    }
    {
        float r = 0.f, g = 0.f, b = 0.f;
        if (b1 >= 0) { float4 c = g_COL[b1]; r = c.x; g = c.y; b = c.z; }
        int ry = HH - 1 - (y0 + 16);
        float d0 = r - image_ref[0*HH*WW + ry*WW + x];
        float d1 = g - image_ref[1*HH*WW + ry*WW + x];
        float d2 = b - image_ref[2*HH*WW + ry*WW + x];
        loss += d0*d0 + d1*d1 + d2*d2;
    }

    __syncthreads();
    sRed[tid] = loss;
    __syncthreads();
    #pragma unroll
    for (int s = 128; s > 0; s >>= 1) {
        if (tid < s) sRed[tid] += sRed[tid + s];
        __syncthreads();
    }
    if (tid == 0) g_partials[blockIdx.y * gridDim.x + blockIdx.x] = sRed[0];
}

// ---------------- kernel 6: final deterministic reduction ----------------
__global__ void k_reduce(float* __restrict__ out) {
    __shared__ float red[256];
    float s = 0.f;
    for (int i = threadIdx.x; i < NBLK; i += 256) s += g_partials[i];
    red[threadIdx.x] = s;
    __syncthreads();
    #pragma unroll
    for (int st = 128; st > 0; st >>= 1) {
        if (threadIdx.x < st) red[threadIdx.x] += red[threadIdx.x + st];
        __syncthreads();
    }
    if (threadIdx.x == 0) out[0] = red[0];
}

// ---------------- entry point ----------------
extern "C" void kernel_launch(void* const* d_in, const int* in_sizes, int n_in,
                              void* d_out, int out_size) {
    const float* v         = (const float*)d_in[0];   // (1, V, 3)
    const int*   faces     = (const int*)  d_in[1];   // (1, F, 3)
    const float* tex       = (const float*)d_in[2];   // (1, F, 2,2,2,3)
    const float* campos    = (const float*)d_in[3];   // (3,)
    const float* camup     = (const float*)d_in[4];   // (3,)
    const float* image_ref = (const float*)d_in[5];   // (1, 3, H, W)

    int nV = in_sizes[0] / 3;
    int nF = in_sizes[1] / 3;

    k_verts<<<1, 256>>>(v, campos, camup, nV);
    k_faces<<<(nF + 255) / 256, 256>>>(faces, tex, nF);
    k_scan<<<1, 32>>>();
    k_scatter<<<(nF + 255) / 256, 256>>>(nF);
    k_render<<<dim3(NBX, NBY), dim3(16, 16)>>>(image_ref, nF);
    k_reduce<<<1, 256>>>((float*)d_out);
}

// round 9
// speedup vs baseline: 2.8652x; 1.0375x over previous
#include <cuda_runtime.h>
#include <math.h>

// Problem constants (fixed by the dataset)
#define HH 512
#define WW 512
#define MAXV 2048
#define MAXF 4096
#define VIEW_TAN 0.5773502691896258f   // tan(30 deg)
#define NEARP 0.1f
#define BIGZ 1.0e10f
#define CH 256          // faces per culling chunk (= block size)
#define NBUK 256        // depth buckets
#define TILE_W 16
#define TILE_H 32       // 2 pixels per thread in y
#define NBX (WW / TILE_W)   // 32
#define NBY (HH / TILE_H)   // 16
#define NBLK (NBX * NBY)    // 512

// ---------------- device scratch (no allocations allowed) ----------------
__device__ float4 g_FA[MAXF];
__device__ float4 g_FB[MAXF];
__device__ float4 g_FC[MAXF];
__device__ float4 g_BB[MAXF];
__device__ float4 g_COL[MAXF];
__device__ float  g_zmin[MAXF];
__device__ int    g_bkt[MAXF];
// bucket-sorted copies
__device__ float4 g_FA2[MAXF];
__device__ float4 g_FB2[MAXF];
__device__ float4 g_FC2[MAXF];
__device__ float4 g_BB2[MAXF];
__device__ int    g_idx2[MAXF];  // original face index
__device__ float  g_zminS[MAXF]; // ACTUAL face zmin per sorted slot
__device__ float  g_lbS[MAXF];   // monotone bucket lower bound per slot
__device__ float  g_vzlo, g_vzhi;
__device__ float  g_partials[NBLK];
__device__ int    g_done;

// =============== kernel 1: verts (redundant per block) + face setup =======
__global__ __launch_bounds__(256)
void k_prep(const float* __restrict__ v,
            const int* __restrict__ faces,
            const float* __restrict__ tex,
            const float* __restrict__ campos,
            const float* __restrict__ camup,
            int nV, int nF) {
    __shared__ float svx[MAXV], svy[MAXV], svz[MAXV];
    __shared__ float sR[9], sEye[3];
    __shared__ float sLo[256], sHi[256];

    const int tid = threadIdx.x;
    if (tid == 0) {
        float ex = campos[0], ey = campos[1], ez = campos[2];
        float nx = -ex, ny = -ey, nz = -ez;
        float nl = sqrtf(nx*nx + ny*ny + nz*nz) + 1e-12f;
        float zx = nx/nl, zy = ny/nl, zz = nz/nl;
        float ux = camup[0], uy = camup[1], uz = camup[2];
        float ul = sqrtf(ux*ux + uy*uy + uz*uz) + 1e-12f;
        ux /= ul; uy /= ul; uz /= ul;
        float cx = uy*zz - uz*zy;
        float cy = uz*zx - ux*zz;
        float cz = ux*zy - uy*zx;
        float cl = sqrtf(cx*cx + cy*cy + cz*cz) + 1e-12f;
        float xx = cx/cl, xy = cy/cl, xz = cz/cl;
        float yx = zy*xz - zz*xy;
        float yy = zz*xx - zx*xz;
        float yz = zx*xy - zy*xx;
        sR[0]=xx; sR[1]=xy; sR[2]=xz;
        sR[3]=yx; sR[4]=yy; sR[5]=yz;
        sR[6]=zx; sR[7]=zy; sR[8]=zz;
        sEye[0]=ex; sEye[1]=ey; sEye[2]=ez;
        if (blockIdx.x == 0) g_done = 0;   // reset render's reduce counter
    }
    __syncthreads();

    // every block transforms ALL vertices into its own smem (identical results)
    float lo = 3.3e38f, hi = -3.3e38f;
    for (int i = tid; i < nV; i += 256) {
        float ax = v[3*i+0] - sEye[0];
        float ay = v[3*i+1] - sEye[1];
        float az = v[3*i+2] - sEye[2];
        float cxx = sR[0]*ax + sR[1]*ay + sR[2]*az;
        float cyy = sR[3]*ax + sR[4]*ay + sR[5]*az;
        float czz = sR[6]*ax + sR[7]*ay + sR[8]*az;
        float d = czz * VIEW_TAN + 1e-12f;
        svx[i] = cxx / d;
        svy[i] = cyy / d;
        svz[i] = czz;
        lo = fminf(lo, czz);
        hi = fmaxf(hi, czz);
    }
    sLo[tid] = lo; sHi[tid] = hi;
    __syncthreads();
    for (int s = 128; s > 0; s >>= 1) {
        if (tid < s) {
            sLo[tid] = fminf(sLo[tid], sLo[tid + s]);
            sHi[tid] = fmaxf(sHi[tid], sHi[tid + s]);
        }
        __syncthreads();
    }
    const float vzlo = sLo[0];
    const float vzw  = sHi[0] - sLo[0];
    if (tid == 0 && blockIdx.x == 0) { g_vzlo = vzlo; g_vzhi = sHi[0]; }

    // one face per thread
    int f = blockIdx.x * 256 + tid;
    if (f >= nF) return;

    int i0 = faces[3*f+0], i1 = faces[3*f+1], i2 = faces[3*f+2];
    float p0x = svx[i0], p0y = svy[i0], z0 = svz[i0];
    float p1x = svx[i1], p1y = svy[i1], z1 = svz[i1];
    float p2x = svx[i2], p2y = svy[i2], z2 = svz[i2];

    float area = (p1x-p0x)*(p2y-p0y) - (p1y-p0y)*(p2x-p0x);
    float zmn = fminf(z0, fminf(z1, z2));
    float zmx = fmaxf(z0, fmaxf(z1, z2));

    float4 FA, FB, FC, BB;
    bool live = (fabsf(area) > 1e-8f) && (zmx > NEARP);
    if (live) {
        float s   = (area > 0.0f) ? 1.0f : -1.0f;
        float inv = 1.0f / fabsf(area);
        float e0x = (p2x-p1x)*s, e0y = (p2y-p1y)*s;
        float A0 = -e0y, B0 = e0x, C0 = e0y*p1x - e0x*p1y;
        float e1x = (p0x-p2x)*s, e1y = (p0y-p2y)*s;
        float A1 = -e1y, B1 = e1x, C1 = e1y*p2x - e1x*p2y;
        float e2x = (p1x-p0x)*s, e2y = (p1y-p0y)*s;
        float A2 = -e2y, B2 = e2x, C2 = e2y*p0x - e2x*p0y;
        FA = make_float4(A0, B0, C0, A1);
        FB = make_float4(B1, C1, A2, B2);
        FC = make_float4(C2, z0*inv, z1*inv, z2*inv);
        BB = make_float4(fminf(p0x, fminf(p1x, p2x)),
                         fminf(p0y, fminf(p1y, p2y)),
                         fmaxf(p0x, fmaxf(p1x, p2x)),
                         fmaxf(p0y, fmaxf(p1y, p2y)));
    } else {
        FA = make_float4(0.f, 0.f, -1.f, 0.f);
        FB = make_float4(0.f, -1.f, 0.f, 0.f);
        FC = make_float4(-1.f, 0.f, 0.f, 0.f);
        BB = make_float4(2e9f, 2e9f, -2e9f, -2e9f);
        zmn = 3e38f;
    }
    g_FA[f] = FA; g_FB[f] = FB; g_FC[f] = FC; g_BB[f] = BB;
    g_zmin[f] = zmn;

    int b;
    if (live) {
        float invw = (vzw > 0.f) ? ((float)NBUK / vzw) : 0.f;
        b = (int)((zmn - vzlo) * invw);
        b = max(0, min(NBUK - 1, b));
    } else {
        b = NBUK;
    }
    g_bkt[f] = b;

    const float* t = tex + (size_t)f * 24;
    float r = 0.f, g = 0.f, bl = 0.f;
    #pragma unroll
    for (int k = 0; k < 8; k++) {
        r += t[3*k+0]; g += t[3*k+1]; bl += t[3*k+2];
    }
    g_COL[f] = make_float4(r*0.125f, g*0.125f, bl*0.125f, 0.f);
}

// ======= kernel 2: deterministic rank-based scatter (no global atomics) ====
__global__ __launch_bounds__(256)
void k_scatter2(int nF) {
    __shared__ int sHist[NBUK + 1];   // total per-bucket counts
    __shared__ int sBase[NBUK + 1];   // per-bucket counts before this slice
    __shared__ int sOffE[NBUK + 2];   // exclusive scan of totals
    __shared__ int sSliceB[256];

    const int tid = threadIdx.x;
    const int sliceStart = blockIdx.x * 256;

    for (int i = tid; i <= NBUK; i += 256) { sHist[i] = 0; sBase[i] = 0; }
    __syncthreads();

    for (int i = tid; i < nF; i += 256) {
        int b = g_bkt[i];
        atomicAdd(&sHist[b], 1);
        if (i < sliceStart) atomicAdd(&sBase[b], 1);
    }
    __syncthreads();

    // exclusive scan of sHist by warp 0
    if (tid < 32) {
        int acc = 0;
        for (int base = 0; base <= NBUK; base += 32) {
            int i = base + tid;
            int vv = (i <= NBUK) ? sHist[i] : 0;
            int sc = vv;
            #pragma unroll
            for (int d = 1; d < 32; d <<= 1) {
                int n = __shfl_up_sync(0xffffffffu, sc, d);
                if (tid >= d) sc += n;
            }
            if (i <= NBUK) sOffE[i + 1] = acc + sc;
            acc += __shfl_sync(0xffffffffu, sc, 31);
        }
        if (tid == 0) sOffE[0] = 0;
    }

    int f = sliceStart + tid;
    int myb = (f < nF) ? g_bkt[f] : -1;
    sSliceB[tid] = myb;
    __syncthreads();

    if (f >= nF) return;
    // rank among earlier same-bucket faces within this slice (order-preserving)
    int rank = 0;
    for (int j = 0; j < tid; j++) rank += (sSliceB[j] == myb);

    int pos = sOffE[myb] + sBase[myb] + rank;
    g_FA2[pos] = g_FA[f];
    g_FB2[pos] = g_FB[f];
    g_FC2[pos] = g_FC[f];
    g_BB2[pos] = g_BB[f];
    g_idx2[pos] = f;
    g_zminS[pos] = g_zmin[f];
    float lb;
    if (myb >= NBUK) {
        lb = 3e38f;
    } else {
        float w = g_vzhi - g_vzlo;
        lb = g_vzlo + (float)myb * w * (1.0f / NBUK) - 1e-5f;
    }
    g_lbS[pos] = lb;
}

// ====== kernel 3: cull + front-to-back rasterize + loss + final reduce =====
__global__ __launch_bounds__(256)
void k_render(const float* __restrict__ image_ref, int nF,
              float* __restrict__ out) {
    __shared__ float4 sA[CH];
    __shared__ float4 sB[CH];
    __shared__ float4 sC[CH];
    __shared__ float  sZm[CH];
    __shared__ int    sIdx[CH];
    __shared__ int    sCnt;
    __shared__ float  sWmax[8];
    __shared__ float  sBmax;
    __shared__ float  sRed[256];
    __shared__ int    sIsLast;

    const int tx = threadIdx.x, ty = threadIdx.y;
    const int tid = ty * 16 + tx;
    const int wid = tid >> 5;
    const int x  = blockIdx.x * TILE_W + tx;
    const int y0 = blockIdx.y * TILE_H + ty;
    const int bid = blockIdx.y * gridDim.x + blockIdx.x;

    const float px  = (x  + 0.5f) * (2.0f / WW) - 1.0f;
    const float py0 = 1.0f - (y0 + 0.5f) * (2.0f / HH);
    const float dpy = -16.0f * (2.0f / HH);

    const float txmin = (blockIdx.x * TILE_W + 0.5f) * (2.0f / WW) - 1.0f;
    const float txmax = (blockIdx.x * TILE_W + TILE_W - 0.5f) * (2.0f / WW) - 1.0f;
    const float tymax = 1.0f - (blockIdx.y * TILE_H + 0.5f) * (2.0f / HH);
    const float tymin = 1.0f - (blockIdx.y * TILE_H + TILE_H - 0.5f) * (2.0f / HH);
    const float tcx = 0.5f * (txmin + txmax);
    const float tcy = 0.5f * (tymin + tymax);
    const float thx = 0.5f * (txmax - txmin);
    const float thy = 0.5f * (tymax - tymin);

    float zb0 = BIGZ, zb1 = BIGZ;
    int   b0  = -1,   b1  = -1;

    if (tid == 0) sBmax = BIGZ;
    __syncthreads();

    for (int base = 0; base < nF; base += CH) {
        float zCap = sBmax;
        if (g_lbS[base] > zCap) break;

        if (tid == 0) sCnt = 0;
        __syncthreads();

        int f = base + tid;
        if (f < nF) {
            float4 bb = g_BB2[f];
            float zmn = g_zminS[f];
            bool ok = (bb.x <= txmax) && (bb.z >= txmin) &&
                      (bb.y <= tymax) && (bb.w >= tymin) &&
                      (zmn <= zCap);
            if (ok) {
                float4 fa = g_FA2[f];
                float4 fb = g_FB2[f];
                float4 fc = g_FC2[f];
                float u0c = fmaf(fa.x, tcx, fmaf(fa.y, tcy, fa.z));
                float m0  = fmaf(fabsf(fa.x), thx, fmaf(fabsf(fa.y), thy, u0c));
                float u1c = fmaf(fa.w, tcx, fmaf(fb.x, tcy, fb.y));
                float m1  = fmaf(fabsf(fa.w), thx, fmaf(fabsf(fb.x), thy, u1c));
                float u2c = fmaf(fb.z, tcx, fmaf(fb.w, tcy, fc.x));
                float m2  = fmaf(fabsf(fb.z), thx, fmaf(fabsf(fb.w), thy, u2c));
                bool keep = (m0 >= -1e-5f * fmaxf(1.0f, fabsf(u0c))) &&
                            (m1 >= -1e-5f * fmaxf(1.0f, fabsf(u1c))) &&
                            (m2 >= -1e-5f * fmaxf(1.0f, fabsf(u2c)));
                if (keep) {
                    int p = atomicAdd(&sCnt, 1);
                    sIdx[p] = g_idx2[f];
                    sZm[p]  = zmn;
                    sA[p]   = fa;
                    sB[p]   = fb;
                    sC[p]   = fc;
                }
            }
        }
        __syncthreads();
        int cnt = sCnt;

        float w = fmaxf(zb0, zb1);
        #pragma unroll
        for (int off = 16; off > 0; off >>= 1)
            w = fmaxf(w, __shfl_xor_sync(0xffffffffu, w, off));

        for (int i = 0; i < cnt; i++) {
            if (sZm[i] > w) continue;
            float4 fa = sA[i];
            float4 fb = sB[i];
            float4 fc = sC[i];
            int    fi = sIdx[i];
            float u0 = fmaf(fa.x, px, fmaf(fa.y, py0, fa.z));
            float u1 = fmaf(fa.w, px, fmaf(fb.x, py0, fb.y));
            float u2 = fmaf(fb.z, px, fmaf(fb.w, py0, fc.x));
            float z  = fmaf(u0, fc.y, fmaf(u1, fc.z, u2 * fc.w));
            float mm = fminf(u0, fminf(u1, u2));
            if (mm >= 0.0f && z > NEARP &&
                (z < zb0 || (z == zb0 && fi < b0))) {
                zb0 = z; b0 = fi;
            }
            float v0 = fmaf(fa.y, dpy, u0);
            float v1 = fmaf(fb.x, dpy, u1);
            float v2 = fmaf(fb.w, dpy, u2);
            float z2 = fmaf(v0, fc.y, fmaf(v1, fc.z, v2 * fc.w));
            float m2 = fminf(v0, fminf(v1, v2));
            if (m2 >= 0.0f && z2 > NEARP &&
                (z2 < zb1 || (z2 == zb1 && fi < b1))) {
                zb1 = z2; b1 = fi;
            }
        }

        float m = fmaxf(zb0, zb1);
        #pragma unroll
        for (int off = 16; off > 0; off >>= 1)
            m = fmaxf(m, __shfl_xor_sync(0xffffffffu, m, off));
        if ((tid & 31) == 0) sWmax[wid] = m;
        __syncthreads();
        if (tid == 0) {
            float bm = sWmax[0];
            #pragma unroll
            for (int k = 1; k < 8; k++) bm = fmaxf(bm, sWmax[k]);
            sBmax = bm;
        }
        __syncthreads();
    }

    float loss = 0.f;
    {
        float r = 0.f, g = 0.f, b = 0.f;
        if (b0 >= 0) { float4 c = g_COL[b0]; r = c.x; g = c.y; b = c.z; }
        int ry = HH - 1 - y0;
        float d0 = r - image_ref[0*HH*WW + ry*WW + x];
        float d1 = g - image_ref[1*HH*WW + ry*WW + x];
        float d2 = b - image_ref[2*HH*WW + ry*WW + x];
        loss += d0*d0 + d1*d1 + d2*d2;
    }
    {
        float r = 0.f, g = 0.f, b = 0.f;
        if (b1 >= 0) { float4 c = g_COL[b1]; r = c.x; g = c.y; b = c.z; }
        int ry = HH - 1 - (y0 + 16);
        float d0 = r - image_ref[0*HH*WW + ry*WW + x];
        float d1 = g - image_ref[1*HH*WW + ry*WW + x];
        float d2 = b - image_ref[2*HH*WW + ry*WW + x];
        loss += d0*d0 + d1*d1 + d2*d2;
    }

    __syncthreads();
    sRed[tid] = loss;
    __syncthreads();
    #pragma unroll
    for (int s = 128; s > 0; s >>= 1) {
        if (tid < s) sRed[tid] += sRed[tid + s];
        __syncthreads();
    }
    if (tid == 0) {
        g_partials[bid] = sRed[0];
        __threadfence();
        int prev = atomicAdd(&g_done, 1);
        sIsLast = (prev == NBLK - 1) ? 1 : 0;
    }
    __syncthreads();

    // last block performs the final deterministic reduction
    if (sIsLast) {
        volatile float* vp = (volatile float*)g_partials;
        float s = vp[tid] + vp[tid + 256];
        sRed[tid] = s;
        __syncthreads();
        #pragma unroll
        for (int st = 128; st > 0; st >>= 1) {
            if (tid < st) sRed[tid] += sRed[tid + st];
            __syncthreads();
        }
        if (tid == 0) out[0] = sRed[0];
    }
}

// ---------------- entry point ----------------
extern "C" void kernel_launch(void* const* d_in, const int* in_sizes, int n_in,
                              void* d_out, int out_size) {
    const float* v         = (const float*)d_in[0];   // (1, V, 3)
    const int*   faces     = (const int*)  d_in[1];   // (1, F, 3)
    const float* tex       = (const float*)d_in[2];   // (1, F, 2,2,2,3)
    const float* campos    = (const float*)d_in[3];   // (3,)
    const float* camup     = (const float*)d_in[4];   // (3,)
    const float* image_ref = (const float*)d_in[5];   // (1, 3, H, W)

    int nV = in_sizes[0] / 3;
    int nF = in_sizes[1] / 3;

    k_prep<<<(nF + 255) / 256, 256>>>(v, faces, tex, campos, camup, nV, nF);
    k_scatter2<<<(nF + 255) / 256, 256>>>(nF);
    k_render<<<dim3(NBX, NBY), dim3(16, 16)>>>(image_ref, nF, (float*)d_out);
}